// round 1
// baseline (speedup 1.0000x reference)
#include <cuda_runtime.h>
#include <math.h>

#define DEVFN __device__ __forceinline__

constexpr int Bb = 8, Ss = 2048, Dd = 1024, Zz = 128, Hh = 2048, Nn = 16, II = 4096, MPc = 2048;
constexpr int SB = Ss * Bb;                 // 16384 tokens
constexpr float EPS = 1e-3f;
constexpr float SCALING = 0.08838834764831843f;  // Z^-0.5

// ---------------- scratch (device globals; no allocations allowed) ----------------
__device__ float g_xn[(size_t)SB * Dd];     // LN(x), (S,B,D) rows m=s*B+b
__device__ float g_mx[(size_t)SB * Dd];     // silu(ema), same layout
__device__ float g_u [(size_t)SB * Dd];
__device__ float g_hx[(size_t)SB * Dd];
__device__ float g_q [(size_t)Bb * Ss * Zz];   // (B,S,Z)
__device__ float g_k [(size_t)Bb * Ss * Zz];   // (B,S,Z)
__device__ float g_vb[(size_t)Bb * Ss * Hh];   // (B,S,H)
__device__ float g_r [(size_t)SB * Hh];        // (S,B,H) rows m
__device__ float g_sc[(size_t)Bb * Ss * Ss];   // attention scores (B,S,S)
__device__ float g_hb[(size_t)Bb * Ss * Hh];   // attn @ v, (B,S,H)
__device__ float g_hr[(size_t)SB * Hh];        // h*r, (S,B,H) rows m
__device__ float g_h2[(size_t)SB * Dd];        // silu(hx + hr@h_w + h_b)
__device__ float g_ol[(size_t)SB * Dd];        // LN(gated), rows b*S+s  (B,S,D)
__device__ float g_in[(size_t)SB * II];        // relu FFN inner

// ---------------- helpers ----------------
DEVFN float sigm(float x) { return 1.f / (1.f + __expf(-x)); }
DEVFN float silu(float x) { return x / (1.f + __expf(-x)); }

DEVFN float warpSum(float v) {
#pragma unroll
    for (int o = 16; o; o >>= 1) v += __shfl_xor_sync(0xffffffffu, v, o);
    return v;
}
DEVFN float warpMax(float v) {
#pragma unroll
    for (int o = 16; o; o >>= 1) v = fmaxf(v, __shfl_xor_sync(0xffffffffu, v, o));
    return v;
}
// blockDim.x == 256 assumed for all block reductions
DEVFN void blockSum2(float& a, float& b) {
    __shared__ float sa[8], sb[8];
    float wa = warpSum(a), wb = warpSum(b);
    if ((threadIdx.x & 31) == 0) { sa[threadIdx.x >> 5] = wa; sb[threadIdx.x >> 5] = wb; }
    __syncthreads();
    a = 0.f; b = 0.f;
#pragma unroll
    for (int i = 0; i < 8; i++) { a += sa[i]; b += sb[i]; }
    __syncthreads();
}
DEVFN float blockSum1(float v) {
    __shared__ float s[8];
    float w = warpSum(v);
    if ((threadIdx.x & 31) == 0) s[threadIdx.x >> 5] = w;
    __syncthreads();
    float r = 0.f;
#pragma unroll
    for (int i = 0; i < 8; i++) r += s[i];
    __syncthreads();
    return r;
}
DEVFN float blockMax1(float v) {
    __shared__ float s[8];
    float w = warpMax(v);
    if ((threadIdx.x & 31) == 0) s[threadIdx.x >> 5] = w;
    __syncthreads();
    float r = s[0];
#pragma unroll
    for (int i = 1; i < 8; i++) r = fmaxf(r, s[i]);
    __syncthreads();
    return r;
}

// packed f32x2 FMA (B300; ptxas never auto-fuses — PTX only)
DEVFN unsigned long long pack2(float x, float y) {
    unsigned long long r;
    asm("mov.b64 %0, {%1,%2};" : "=l"(r) : "f"(x), "f"(y));
    return r;
}
DEVFN void fma2(unsigned long long& d, unsigned long long a, unsigned long long b) {
    asm("fma.rn.f32x2 %0, %1, %2, %0;" : "+l"(d) : "l"(a), "l"(b));
}
DEVFN float2 unpack2(unsigned long long v) {
    float2 r;
    asm("mov.b64 {%0,%1}, %2;" : "=f"(r.x), "=f"(r.y) : "l"(v));
    return r;
}

// ---------------- LN1: xn = LN(x), write transposed to (S,B,D) ----------------
__global__ __launch_bounds__(256) void k_ln1(const float* __restrict__ x,
                                             const float* __restrict__ sc,
                                             const float* __restrict__ bi) {
    int m = blockIdx.x;            // b*S + s  (x layout)
    int b = m / Ss, s = m % Ss;
    const float* xr = x + (size_t)m * Dd;
    int t = threadIdx.x;
    float v[4]; float su = 0.f, sq = 0.f;
#pragma unroll
    for (int i = 0; i < 4; i++) { float f = xr[t + 256 * i]; v[i] = f; su += f; sq += f * f; }
    blockSum2(su, sq);
    float mu  = su * (1.f / Dd);
    float inv = rsqrtf(sq * (1.f / Dd) - mu * mu + EPS);
    float* o = g_xn + (size_t)(s * Bb + b) * Dd;
#pragma unroll
    for (int i = 0; i < 4; i++) { int d = t + 256 * i; o[d] = (v[i] - mu) * inv * sc[d] + bi[d]; }
}

// ---------------- EMA: 16-state recurrence scan, one half-warp per (b,d) ----------------
__global__ __launch_bounds__(256) void k_ema(const float* __restrict__ de,
                                             const float* __restrict__ al,
                                             const float* __restrict__ be,
                                             const float* __restrict__ ga,
                                             const float* __restrict__ om) {
    int t = threadIdx.x;
    int lane = t & 15;
    int P = blockIdx.x * 16 + (t >> 4);   // 0..8191 = b*D + d
    int b = P / Dd, d = P % Dd;
    int pi = d * Nn + lane;
    float p    = sigm(de[pi]);
    float q    = 1.f - p * sigm(al[pi]);
    float coef = p * be[pi] * ga[pi] * 0.25f;   // 1/sqrt(16)
    float w = om[d];
    const float* xp = g_xn + (size_t)b * Dd + d;
    float*       op = g_mx + (size_t)b * Dd + d;
    float s = 0.f;
    for (int l = 0; l < Ss; l++) {
        float xv = xp[(size_t)l * (Bb * Dd)];
        s = fmaf(q, s, xv);
        float r = coef * s;
        r += __shfl_xor_sync(0xffffffffu, r, 1);
        r += __shfl_xor_sync(0xffffffffu, r, 2);
        r += __shfl_xor_sync(0xffffffffu, r, 4);
        r += __shfl_xor_sync(0xffffffffu, r, 8);
        if (lane == 0) op[(size_t)l * (Bb * Dd)] = silu(r + xv * w);
    }
}

// ---------------- GEMM (128x128x16, f32x2, fused epilogues) ----------------
struct GemmP {
    const float* A; const float* Bm;
    const float* bias; const float* aux1; const float* aux2;
    float* out;
    int K, N;
    long long sA, sB;
};

enum { EP_V = 0, EP_BASE, EP_SC, EP_HB, EP_H2, EP_RELU, EP_FIN };

template<int EP>
DEVFN void epi(const GemmP& p, int bz, int m, int n, float acc) {
    if (EP == EP_V) {
        float v = silu(acc + p.bias[n]);
        int s = m >> 3, b = m & 7;
        g_vb[((size_t)b * Ss + s) * Hh + n] = v;
    } else if (EP == EP_BASE) {
        float a = acc + p.bias[n];
        if (n < Dd) {
            g_u[(size_t)m * Dd + n] = sigm(a);
        } else if (n < Dd + Zz) {
            float z = silu(a); int zi = n - Dd;
            int s = m >> 3, b = m & 7;
            size_t o = ((size_t)b * Ss + s) * Zz + zi;
            g_q[o] = z * p.aux1[zi]      + p.aux2[zi];
            g_k[o] = z * p.aux1[Zz + zi] + p.aux2[Zz + zi];
        } else if (n < Dd + Zz + Hh) {
            g_r[(size_t)m * Hh + (n - Dd - Zz)] = silu(a);
        } else {
            g_hx[(size_t)m * Dd + (n - Dd - Zz - Hh)] = a;
        }
    } else if (EP == EP_SC) {
        g_sc[((size_t)bz * Ss + m) * Ss + n] = acc * SCALING + p.aux1[MPc - 1 + n - m];
    } else if (EP == EP_HB) {
        g_hb[((size_t)bz * Ss + m) * Hh + n] = acc;
    } else if (EP == EP_H2) {
        g_h2[(size_t)m * Dd + n] = silu(acc + p.bias[n] + p.aux1[(size_t)m * Dd + n]);
    } else if (EP == EP_RELU) {
        g_in[(size_t)m * II + n] = fmaxf(acc + p.bias[n], 0.f);
    } else { // EP_FIN
        p.out[(size_t)m * Dd + n] = acc + p.bias[n] + p.aux1[(size_t)m * Dd + n];
    }
}

template<int EP, bool TB>
__global__ __launch_bounds__(256) void k_gemm(GemmP p) {
    __shared__ float As[16][132];
    __shared__ float Bs[16][132];
    int bz = blockIdx.z;
    const float* A  = p.A  + (size_t)bz * p.sA;
    const float* Bm = p.Bm + (size_t)bz * p.sB;
    int m0 = blockIdx.y * 128, n0 = blockIdx.x * 128;
    int t = threadIdx.x;
    int aR = t >> 2, aC = (t & 3) * 4;
    int bR = t >> 5, bC = (t & 31) * 4;
    unsigned long long acc[8][4];
#pragma unroll
    for (int i = 0; i < 8; i++)
#pragma unroll
        for (int j = 0; j < 4; j++) acc[i][j] = 0ull;
    int tx = t & 15, ty = t >> 4;

    for (int k0 = 0; k0 < p.K; k0 += 16) {
#pragma unroll
        for (int i = 0; i < 2; i++) {
            int r = aR + i * 64;
            float4 a4 = *(const float4*)(A + (size_t)(m0 + r) * p.K + k0 + aC);
            As[aC][r] = a4.x; As[aC + 1][r] = a4.y; As[aC + 2][r] = a4.z; As[aC + 3][r] = a4.w;
        }
        if (TB) {
#pragma unroll
            for (int i = 0; i < 2; i++) {
                int r = aR + i * 64;
                float4 b4 = *(const float4*)(Bm + (size_t)(n0 + r) * p.K + k0 + aC);
                Bs[aC][r] = b4.x; Bs[aC + 1][r] = b4.y; Bs[aC + 2][r] = b4.z; Bs[aC + 3][r] = b4.w;
            }
        } else {
#pragma unroll
            for (int i = 0; i < 2; i++) {
                int r = bR + i * 8;
                *(float4*)&Bs[r][bC] = *(const float4*)(Bm + (size_t)(k0 + r) * p.N + n0 + bC);
            }
        }
        __syncthreads();
#pragma unroll
        for (int k = 0; k < 16; k++) {
            float4 a0 = *(const float4*)&As[k][ty * 8];
            float4 a1 = *(const float4*)&As[k][ty * 8 + 4];
            ulonglong2 b0 = *(const ulonglong2*)&Bs[k][tx * 8];
            ulonglong2 b1 = *(const ulonglong2*)&Bs[k][tx * 8 + 4];
            unsigned long long bb[4] = { b0.x, b0.y, b1.x, b1.y };
            float ar[8] = { a0.x, a0.y, a0.z, a0.w, a1.x, a1.y, a1.z, a1.w };
#pragma unroll
            for (int i = 0; i < 8; i++) {
                unsigned long long ai = pack2(ar[i], ar[i]);
#pragma unroll
                for (int j = 0; j < 4; j++) fma2(acc[i][j], ai, bb[j]);
            }
        }
        __syncthreads();
    }

    int gm = m0 + ty * 8, gn = n0 + tx * 8;
#pragma unroll
    for (int i = 0; i < 8; i++)
#pragma unroll
        for (int j = 0; j < 4; j++) {
            float2 v = unpack2(acc[i][j]);
            epi<EP>(p, bz, gm + i, gn + 2 * j,     v.x);
            epi<EP>(p, bz, gm + i, gn + 2 * j + 1, v.y);
        }
}

// ---------------- softmax over rows of 2048 ----------------
__global__ __launch_bounds__(256) void k_softmax() {
    size_t row = blockIdx.x;
    float* rp = g_sc + row * Ss;
    int t = threadIdx.x;
    float v[8]; float mx = -1e30f;
#pragma unroll
    for (int i = 0; i < 8; i++) { v[i] = rp[t + 256 * i]; mx = fmaxf(mx, v[i]); }
    mx = blockMax1(mx);
    float su = 0.f;
#pragma unroll
    for (int i = 0; i < 8; i++) { v[i] = __expf(v[i] - mx); su += v[i]; }
    su = blockSum1(su);
    float inv = 1.f / su;
#pragma unroll
    for (int i = 0; i < 8; i++) rp[t + 256 * i] = v[i] * inv;
}

// ---------------- hr = h (permuted) * r ----------------
__global__ __launch_bounds__(256) void k_hr() {
    size_t i = ((size_t)blockIdx.x * blockDim.x + threadIdx.x) * 4;
    size_t m = i / Hh; int h = (int)(i % Hh);
    int s = (int)(m >> 3), b = (int)(m & 7);
    float4 hb4 = *(const float4*)&g_hb[((size_t)b * Ss + s) * Hh + h];
    float4 r4  = *(const float4*)&g_r[i];
    float4 o;
    o.x = hb4.x * r4.x; o.y = hb4.y * r4.y; o.z = hb4.z * r4.z; o.w = hb4.w * r4.w;
    *(float4*)&g_hr[i] = o;
}

// ---------------- gate + LN2: out = LN(xn + u*(h2 - xn)), write (B,S,D) ----------------
__global__ __launch_bounds__(256) void k_gateln(const float* __restrict__ sc,
                                                const float* __restrict__ bi) {
    int m = blockIdx.x;            // s*B + b
    int s = m >> 3, b = m & 7;
    int t = threadIdx.x;
    size_t base = (size_t)m * Dd;
    float g[4]; float su = 0.f, sq = 0.f;
#pragma unroll
    for (int i = 0; i < 4; i++) {
        int d = t + 256 * i;
        float xn = g_xn[base + d];
        float val = xn + g_u[base + d] * (g_h2[base + d] - xn);
        g[i] = val; su += val; sq += val * val;
    }
    blockSum2(su, sq);
    float mu  = su * (1.f / Dd);
    float inv = rsqrtf(sq * (1.f / Dd) - mu * mu + EPS);
    float* o = g_ol + ((size_t)b * Ss + s) * Dd;
#pragma unroll
    for (int i = 0; i < 4; i++) { int d = t + 256 * i; o[d] = (g[i] - mu) * inv * sc[d] + bi[d]; }
}

// ---------------- launch ----------------
extern "C" void kernel_launch(void* const* d_in, const int* in_sizes, int n_in,
                              void* d_out, int out_size) {
    (void)in_sizes; (void)n_in; (void)out_size;
    const float* x    = (const float*)d_in[0];
    const float* ln_s = (const float*)d_in[1];
    const float* ln_b = (const float*)d_in[2];
    const float* v_w  = (const float*)d_in[3];
    const float* v_b  = (const float*)d_in[4];
    const float* mx_w = (const float*)d_in[5];
    const float* mx_b = (const float*)d_in[6];
    const float* h_w  = (const float*)d_in[7];
    const float* h_b  = (const float*)d_in[8];
    const float* gamma= (const float*)d_in[9];
    const float* beta = (const float*)d_in[10];
    const float* rel  = (const float*)d_in[11];
    const float* e_d  = (const float*)d_in[12];
    const float* e_a  = (const float*)d_in[13];
    const float* e_b  = (const float*)d_in[14];
    const float* e_g  = (const float*)d_in[15];
    const float* e_o  = (const float*)d_in[16];
    const float* f_s  = (const float*)d_in[17];
    const float* f_b  = (const float*)d_in[18];
    const float* w1   = (const float*)d_in[19];
    const float* b1   = (const float*)d_in[20];
    const float* w2   = (const float*)d_in[21];
    const float* b2   = (const float*)d_in[22];

    float *p_xn, *p_mx, *p_q, *p_k, *p_vb, *p_sc, *p_hr, *p_hx, *p_ol, *p_in;
    cudaGetSymbolAddress((void**)&p_xn, g_xn);
    cudaGetSymbolAddress((void**)&p_mx, g_mx);
    cudaGetSymbolAddress((void**)&p_q,  g_q);
    cudaGetSymbolAddress((void**)&p_k,  g_k);
    cudaGetSymbolAddress((void**)&p_vb, g_vb);
    cudaGetSymbolAddress((void**)&p_sc, g_sc);
    cudaGetSymbolAddress((void**)&p_hr, g_hr);
    cudaGetSymbolAddress((void**)&p_hx, g_hx);
    cudaGetSymbolAddress((void**)&p_ol, g_ol);
    cudaGetSymbolAddress((void**)&p_in, g_in);

    // 1. LN + transpose
    k_ln1<<<SB, 256>>>(x, ln_s, ln_b);
    // 2. EMA scan
    k_ema<<<(Bb * Dd) / 16, 256>>>(e_d, e_a, e_b, e_g, e_o);
    // 3. v = silu(xn @ v_w + v_b) -> (B,S,H)
    {
        GemmP p; p.A = p_xn; p.Bm = v_w; p.bias = v_b; p.aux1 = nullptr; p.aux2 = nullptr;
        p.out = nullptr; p.K = Dd; p.N = Hh; p.sA = 0; p.sB = 0;
        k_gemm<EP_V, false><<<dim3(Hh / 128, SB / 128, 1), 256>>>(p);
    }
    // 4. base = mx @ mx_w + mx_b, split into u / (q,k) / r / hx
    {
        GemmP p; p.A = p_mx; p.Bm = mx_w; p.bias = mx_b; p.aux1 = gamma; p.aux2 = beta;
        p.out = nullptr; p.K = Dd; p.N = Dd + Zz + Hh + Dd; p.sA = 0; p.sB = 0;
        k_gemm<EP_BASE, false><<<dim3((Dd + Zz + Hh + Dd) / 128, SB / 128, 1), 256>>>(p);
    }
    // 5. scores = scaling * q @ k^T + rel_pos bias   (batched over B)
    {
        GemmP p; p.A = p_q; p.Bm = p_k; p.bias = nullptr; p.aux1 = rel; p.aux2 = nullptr;
        p.out = nullptr; p.K = Zz; p.N = Ss; p.sA = (long long)Ss * Zz; p.sB = (long long)Ss * Zz;
        k_gemm<EP_SC, true><<<dim3(Ss / 128, Ss / 128, Bb), 256>>>(p);
    }
    // 6. softmax rows
    k_softmax<<<Bb * Ss, 256>>>();
    // 7. hb = attn @ vb   (batched)
    {
        GemmP p; p.A = p_sc; p.Bm = p_vb; p.bias = nullptr; p.aux1 = nullptr; p.aux2 = nullptr;
        p.out = nullptr; p.K = Ss; p.N = Hh; p.sA = (long long)Ss * Ss; p.sB = (long long)Ss * Hh;
        k_gemm<EP_HB, false><<<dim3(Hh / 128, Ss / 128, Bb), 256>>>(p);
    }
    // 8. hr = h(permute) * r
    k_hr<<<((size_t)SB * Hh / 4) / 256, 256>>>();
    // 9. h2 = silu(hx + hr @ h_w + h_b)
    {
        GemmP p; p.A = p_hr; p.Bm = h_w; p.bias = h_b; p.aux1 = p_hx; p.aux2 = nullptr;
        p.out = nullptr; p.K = Hh; p.N = Dd; p.sA = 0; p.sB = 0;
        k_gemm<EP_H2, false><<<dim3(Dd / 128, SB / 128, 1), 256>>>(p);
    }
    // 10. gate + LN2 (writes (B,S,D) order)
    k_gateln<<<SB, 256>>>(f_s, f_b);
    // 11. inner = relu(out @ w1 + b1)
    {
        GemmP p; p.A = p_ol; p.Bm = w1; p.bias = b1; p.aux1 = nullptr; p.aux2 = nullptr;
        p.out = nullptr; p.K = Dd; p.N = II; p.sA = 0; p.sB = 0;
        k_gemm<EP_RELU, false><<<dim3(II / 128, SB / 128, 1), 256>>>(p);
    }
    // 12. final = inner @ w2 + b2 + out
    {
        GemmP p; p.A = p_in; p.Bm = w2; p.bias = b2; p.aux1 = p_ol; p.aux2 = nullptr;
        p.out = (float*)d_out; p.K = II; p.N = Dd; p.sA = 0; p.sB = 0;
        k_gemm<EP_FIN, false><<<dim3(Dd / 128, SB / 128, 1), 256>>>(p);
    }
}